// round 1
// baseline (speedup 1.0000x reference)
#include <cuda_runtime.h>
#include <math.h>

// ---------------------------------------------------------------------------
// Spatial_SelfAttention baseline (fp32, CUDA cores), sm_103a.
//   q = x@Wq^T, k = x@Wk^T, v = x@Wv^T       (SGEMM, C = A * B^T form)
//   S = scale * q k^T ; A = softmax(S)       (exact, scores resident in smem)
//   O = A v ; out = O@Wo^T + bo
// Outputs: d_out[0 : 8388608]            = out  [B,L,D]
//          d_out[8388608 : +268435456]   = A    [B,H,L,L]   (if out_size fits)
// ---------------------------------------------------------------------------

#define D_MODEL 1024
#define N_HEAD  16
#define HD      64
#define B_SZ    4
#define SEQ     2048
#define M_ROWS  (B_SZ * SEQ)   // 8192

// Scratch (device globals: allocation-free rule)
__device__ float g_q[(size_t)M_ROWS * D_MODEL];
__device__ float g_k[(size_t)M_ROWS * D_MODEL];
__device__ float g_v[(size_t)M_ROWS * D_MODEL];
__device__ float g_o[(size_t)M_ROWS * D_MODEL];

// ---------------------------------------------------------------------------
// SGEMM: C[M,N] = A[M,K] * W[N,K]^T (+ bias), all row-major fp32.
// Block tile 128x128, K-step 16, 256 threads, 8x8 per thread.
// ---------------------------------------------------------------------------
__global__ __launch_bounds__(256) void sgemm128(
    const float* __restrict__ A, const float* __restrict__ Wm,
    float* __restrict__ C, const float* __restrict__ bias)
{
    const int K = D_MODEL, N = D_MODEL;
    __shared__ float As[16][132];
    __shared__ float Bs[16][132];

    const int tid = threadIdx.x;
    const int bm  = blockIdx.y * 128;
    const int bn  = blockIdx.x * 128;
    const int ty  = tid >> 4;   // 0..15
    const int tx  = tid & 15;   // 0..15

    float acc[8][8];
#pragma unroll
    for (int i = 0; i < 8; i++)
#pragma unroll
        for (int j = 0; j < 8; j++) acc[i][j] = 0.f;

    const float* Aptr = A  + (size_t)bm * K;
    const float* Bptr = Wm + (size_t)bn * K;

    for (int kk = 0; kk < K; kk += 16) {
#pragma unroll
        for (int t = tid; t < 512; t += 256) {
            int row = t >> 2, c4 = t & 3;
            float4 va = *(const float4*)(Aptr + (size_t)row * K + kk + c4 * 4);
            As[c4*4+0][row] = va.x; As[c4*4+1][row] = va.y;
            As[c4*4+2][row] = va.z; As[c4*4+3][row] = va.w;
            float4 vb = *(const float4*)(Bptr + (size_t)row * K + kk + c4 * 4);
            Bs[c4*4+0][row] = vb.x; Bs[c4*4+1][row] = vb.y;
            Bs[c4*4+2][row] = vb.z; Bs[c4*4+3][row] = vb.w;
        }
        __syncthreads();
#pragma unroll
        for (int k = 0; k < 16; k++) {
            float a[8], b[8];
            *(float4*)&a[0] = *(const float4*)&As[k][ty * 4];
            *(float4*)&a[4] = *(const float4*)&As[k][64 + ty * 4];
            *(float4*)&b[0] = *(const float4*)&Bs[k][tx * 4];
            *(float4*)&b[4] = *(const float4*)&Bs[k][64 + tx * 4];
#pragma unroll
            for (int i = 0; i < 8; i++)
#pragma unroll
                for (int j = 0; j < 8; j++) acc[i][j] += a[i] * b[j];
        }
        __syncthreads();
    }

    float4 bia0 = make_float4(0.f, 0.f, 0.f, 0.f);
    float4 bia1 = make_float4(0.f, 0.f, 0.f, 0.f);
    if (bias) {
        bia0 = *(const float4*)(bias + bn + tx * 4);
        bia1 = *(const float4*)(bias + bn + 64 + tx * 4);
    }
#pragma unroll
    for (int i = 0; i < 8; i++) {
        int r = bm + ((i < 4) ? (ty * 4 + i) : (64 + ty * 4 + (i - 4)));
        float4 o0 = make_float4(acc[i][0] + bia0.x, acc[i][1] + bia0.y,
                                acc[i][2] + bia0.z, acc[i][3] + bia0.w);
        float4 o1 = make_float4(acc[i][4] + bia1.x, acc[i][5] + bia1.y,
                                acc[i][6] + bia1.z, acc[i][7] + bia1.w);
        *(float4*)(C + (size_t)r * N + bn + tx * 4)      = o0;
        *(float4*)(C + (size_t)r * N + bn + 64 + tx * 4) = o1;
    }
}

// ---------------------------------------------------------------------------
// Attention: block = (16 query rows) x (one b,h). Scores for the full 2048
// keys are smem-resident -> exact softmax, A written to gmem, then O = A*V.
// ---------------------------------------------------------------------------
#define TQ 16
#define NK 256
#define QT_STRIDE 20     // sQT[64][20]   (16B-aligned rows)
#define KT_STRIDE 260    // sKT[64][260]  (16B-aligned rows)
#define V_STRIDE  68     // sV[256][68]

// smem layout (floats):
//   sS  [TQ][SEQ]      : 0        .. 32768
//   sQT [HD][QT_STRIDE]: 32768    .. 34048
//   sU  (union: K^T tile / V tile / O partials): 34048 .. 51456
#define SMEM_FLOATS 51456

__global__ __launch_bounds__(256) void attn_kernel(float* __restrict__ Aout,
                                                   int writeA)
{
    extern __shared__ float sm[];
    float* sS  = sm;
    float* sQT = sm + TQ * SEQ;
    float* sU  = sQT + HD * QT_STRIDE;

    const int tid = threadIdx.x;
    const int qt  = blockIdx.x;          // 0..127
    const int bh  = blockIdx.y;          // 0..63
    const int b   = bh >> 4;
    const int h   = bh & 15;
    const size_t rowbase = (size_t)b * SEQ;
    const int q0  = qt * TQ;
    const float scale = 0.125f;          // 1/sqrt(64)

    // ---- load Q tile transposed: sQT[d][row] ----
    {
        int row = tid & 15;
        int d4  = tid >> 4;
        const float* gq = g_q + (rowbase + q0 + row) * D_MODEL + h * HD + d4 * 4;
        float4 v = *(const float4*)gq;
        sQT[(d4*4+0) * QT_STRIDE + row] = v.x;
        sQT[(d4*4+1) * QT_STRIDE + row] = v.y;
        sQT[(d4*4+2) * QT_STRIDE + row] = v.z;
        sQT[(d4*4+3) * QT_STRIDE + row] = v.w;
    }

    // ---- phase 1: S = scale * q k^T, tile over 256 keys ----
    const int cg = tid & 63;   // col group (4 keys)
    const int rg = tid >> 6;   // row group (4 queries)
    for (int kt = 0; kt < SEQ / NK; kt++) {
        {   // stage K tile transposed: sU[d][s], thread = one key
            const float* gk = g_k + (rowbase + kt * NK + tid) * D_MODEL + h * HD;
#pragma unroll
            for (int d4 = 0; d4 < 16; d4++) {
                float4 v = *(const float4*)(gk + d4 * 4);
                sU[(d4*4+0) * KT_STRIDE + tid] = v.x;
                sU[(d4*4+1) * KT_STRIDE + tid] = v.y;
                sU[(d4*4+2) * KT_STRIDE + tid] = v.z;
                sU[(d4*4+3) * KT_STRIDE + tid] = v.w;
            }
        }
        __syncthreads();
        float acc[4][4];
#pragma unroll
        for (int i = 0; i < 4; i++)
#pragma unroll
            for (int j = 0; j < 4; j++) acc[i][j] = 0.f;
#pragma unroll
        for (int d = 0; d < HD; d++) {
            float a[4], kvec[4];
            *(float4*)a    = *(const float4*)&sQT[d * QT_STRIDE + rg * 4];
            *(float4*)kvec = *(const float4*)&sU[d * KT_STRIDE + cg * 4];
#pragma unroll
            for (int i = 0; i < 4; i++)
#pragma unroll
                for (int j = 0; j < 4; j++) acc[i][j] += a[i] * kvec[j];
        }
#pragma unroll
        for (int i = 0; i < 4; i++) {
            float4 o = make_float4(acc[i][0] * scale, acc[i][1] * scale,
                                   acc[i][2] * scale, acc[i][3] * scale);
            *(float4*)&sS[(rg * 4 + i) * SEQ + kt * NK + cg * 4] = o;
        }
        __syncthreads();
    }

    // ---- phase 2: exact softmax per row (warp w -> rows 2w, 2w+1) ----
    const int warp = tid >> 5, lane = tid & 31;
#pragma unroll
    for (int rr = 0; rr < 2; rr++) {
        int r = warp * 2 + rr;
        float* row = sS + r * SEQ;
        float m = -1e30f;
        for (int s = lane * 4; s < SEQ; s += 128) {
            float4 v = *(const float4*)&row[s];
            m = fmaxf(m, fmaxf(fmaxf(v.x, v.y), fmaxf(v.z, v.w)));
        }
#pragma unroll
        for (int o = 16; o; o >>= 1) m = fmaxf(m, __shfl_xor_sync(0xffffffffu, m, o));
        float sum = 0.f;
        for (int s = lane * 4; s < SEQ; s += 128) {
            float4 v = *(const float4*)&row[s];
            v.x = __expf(v.x - m); v.y = __expf(v.y - m);
            v.z = __expf(v.z - m); v.w = __expf(v.w - m);
            *(float4*)&row[s] = v;
            sum += (v.x + v.y) + (v.z + v.w);
        }
#pragma unroll
        for (int o = 16; o; o >>= 1) sum += __shfl_xor_sync(0xffffffffu, sum, o);
        float inv = 1.0f / sum;
        float* arow = Aout + ((size_t)bh * SEQ + q0 + r) * SEQ;
        for (int s = lane * 4; s < SEQ; s += 128) {
            float4 v = *(const float4*)&row[s];
            v.x *= inv; v.y *= inv; v.z *= inv; v.w *= inv;
            *(float4*)&row[s] = v;
            if (writeA) *(float4*)(arow + s) = v;
        }
    }
    __syncthreads();

    // ---- phase 3: O = A * V, K-split x4 register tiling ----
    const int ks  = tid >> 6;         // 0..3 (key split)
    const int r4  = (tid >> 4) & 3;   // 0..3 (row group)
    const int cg3 = tid & 15;         // 0..15 (col group of 4)
    float oacc[4][4];
#pragma unroll
    for (int i = 0; i < 4; i++)
#pragma unroll
        for (int j = 0; j < 4; j++) oacc[i][j] = 0.f;

    for (int vt = 0; vt < SEQ / NK; vt++) {
#pragma unroll
        for (int t = tid; t < NK * 16; t += 256) {   // stage V tile (row-major)
            int s = t >> 4, d4 = t & 15;
            float4 v = *(const float4*)(g_v + (rowbase + vt * NK + s) * D_MODEL
                                        + h * HD + d4 * 4);
            *(float4*)&sU[s * V_STRIDE + d4 * 4] = v;
        }
        __syncthreads();
#pragma unroll 8
        for (int sl = 0; sl < NK / 4; sl++) {
            int s = ks * (NK / 4) + sl;
            float a[4];
#pragma unroll
            for (int i = 0; i < 4; i++)
                a[i] = sS[(r4 * 4 + i) * SEQ + vt * NK + s];
            float vv[4];
            *(float4*)vv = *(const float4*)&sU[s * V_STRIDE + cg3 * 4];
#pragma unroll
            for (int i = 0; i < 4; i++)
#pragma unroll
                for (int j = 0; j < 4; j++) oacc[i][j] += a[i] * vv[j];
        }
        __syncthreads();
    }

    // reduce the 4 K-split partials through smem
    float* sO = sU;   // [4][16][V_STRIDE]
#pragma unroll
    for (int i = 0; i < 4; i++)
        *(float4*)&sO[((ks * 16) + r4 * 4 + i) * V_STRIDE + cg3 * 4] =
            make_float4(oacc[i][0], oacc[i][1], oacc[i][2], oacc[i][3]);
    __syncthreads();
    for (int t = tid; t < TQ * HD; t += 256) {
        int r = t >> 6, c = t & 63;
        float sumo = sO[(0 * 16 + r) * V_STRIDE + c]
                   + sO[(1 * 16 + r) * V_STRIDE + c]
                   + sO[(2 * 16 + r) * V_STRIDE + c]
                   + sO[(3 * 16 + r) * V_STRIDE + c];
        g_o[(rowbase + q0 + r) * D_MODEL + h * HD + c] = sumo;
    }
}

// ---------------------------------------------------------------------------
extern "C" void kernel_launch(void* const* d_in, const int* in_sizes, int n_in,
                              void* d_out, int out_size)
{
    (void)in_sizes; (void)n_in;
    const float* x  = (const float*)d_in[0];
    // d_in[1] = key_indices (unused by the reference)
    const float* Wq = (const float*)d_in[2];
    const float* Wk = (const float*)d_in[3];
    const float* Wv = (const float*)d_in[4];
    const float* Wo = (const float*)d_in[5];
    const float* bo = (const float*)d_in[6];
    float* out = (float*)d_out;

    float *qp, *kp, *vp, *op;
    cudaGetSymbolAddress((void**)&qp, g_q);
    cudaGetSymbolAddress((void**)&kp, g_k);
    cudaGetSymbolAddress((void**)&vp, g_v);
    cudaGetSymbolAddress((void**)&op, g_o);

    dim3 blk(256);
    dim3 gproj(D_MODEL / 128, M_ROWS / 128);   // (8, 64)

    sgemm128<<<gproj, blk>>>(x, Wq, qp, nullptr);
    sgemm128<<<gproj, blk>>>(x, Wk, kp, nullptr);
    sgemm128<<<gproj, blk>>>(x, Wv, vp, nullptr);

    const size_t OUT_ELEMS = (size_t)M_ROWS * D_MODEL;              // 8388608
    const size_t A_ELEMS   = (size_t)B_SZ * N_HEAD * SEQ * SEQ;     // 268435456
    int writeA = ((size_t)out_size >= OUT_ELEMS + A_ELEMS) ? 1 : 0;
    float* Aout = out + OUT_ELEMS;

    size_t smem_bytes = (size_t)SMEM_FLOATS * sizeof(float);        // 205824
    cudaFuncSetAttribute(attn_kernel,
                         cudaFuncAttributeMaxDynamicSharedMemorySize,
                         (int)smem_bytes);
    attn_kernel<<<dim3(SEQ / TQ, B_SZ * N_HEAD), blk, smem_bytes>>>(Aout, writeA);

    sgemm128<<<gproj, blk>>>(op, Wo, out, bo);
}